// round 14
// baseline (speedup 1.0000x reference)
#include <cuda_runtime.h>
#include <math.h>
#include <stdint.h>

#define H 768
#define R 64
#define E 8
#define T_TOT 16384
#define T_TILE 64

// ---------------- device global scratch -----------------------------------
__device__ int   g_counts[E];
__device__ int   g_toks[E * T_TOT];
__device__ float g_pmax[T_TOT];
__device__ float g_wc[H * E];        // combined router weight (c-interleaved)
__device__ float g_bc[E];            // combined router bias
__device__ float g_w1r[E * H * R];   // tf32-rounded w1
__device__ float g_w2r[E * R * H];   // tf32-rounded w2

// ---------------- helpers ---------------------------------------------------
__device__ __forceinline__ float tf32f(float v) {
    uint32_t r; asm("cvt.rna.tf32.f32 %0, %1;" : "=r"(r) : "f"(v));
    return __uint_as_float(r);
}
__device__ __forceinline__ float gelu(float v) {
    return 0.5f * v * (1.0f + erff(v * 0.70710678118654752f));
}
__device__ __forceinline__ void mma_tf32(float c[4], uint32_t a0, uint32_t a1,
                                         uint32_t a2, uint32_t a3,
                                         uint32_t b0, uint32_t b1) {
    asm volatile(
        "mma.sync.aligned.m16n8k8.row.col.f32.tf32.tf32.f32 "
        "{%0,%1,%2,%3}, {%4,%5,%6,%7}, {%8,%9}, {%0,%1,%2,%3};"
        : "+f"(c[0]), "+f"(c[1]), "+f"(c[2]), "+f"(c[3])
        : "r"(a0), "r"(a1), "r"(a2), "r"(a3), "r"(b0), "r"(b1));
}
#define FB(x) __float_as_uint(x)

__device__ __forceinline__ uint32_t smem_u32(const void* p) {
    uint32_t a;
    asm("{ .reg .u64 t; cvta.to.shared.u64 t, %1; cvt.u32.u64 %0, t; }" : "=r"(a) : "l"(p));
    return a;
}
#define CP16(dst, src) \
    asm volatile("cp.async.cg.shared.global [%0], [%1], 16;" :: "r"(dst), "l"(src))
#define CP_COMMIT() asm volatile("cp.async.commit_group;" ::: "memory")
#define CP_WAIT0()  asm volatile("cp.async.wait_group 0;" ::: "memory")
#define CP_WAIT1()  asm volatile("cp.async.wait_group 1;" ::: "memory")

// ---------------- prep: W_comb + tf32-rounded weight copies -----------------
// blocks 0..23: g_wc/g_bc/counts ; 24..119: round w1 ; 120..215: round w2
__global__ __launch_bounds__(256) void router_prep_kernel(
    const float* __restrict__ enc_w, const float* __restrict__ enc_b,
    const float* __restrict__ sw_w,  const float* __restrict__ sw_b,
    const float* __restrict__ w1,    const float* __restrict__ w2)
{
    const int bid = blockIdx.x, tid = threadIdx.x;
    if (bid < 24) {
        __shared__ float sws[R * E];
        sws[tid]       = sw_w[tid];
        sws[tid + 256] = sw_w[tid + 256];
        __syncthreads();

        const int idx = bid * 256 + tid;
        const int h = idx >> 3, e = idx & 7;
        const float4* ew = (const float4*)(enc_w + (size_t)h * R);
        float4 v[16];
#pragma unroll
        for (int i = 0; i < 16; i++) v[i] = ew[i];
        float acc = 0.f;
#pragma unroll
        for (int i = 0; i < 16; i++) {
            acc = fmaf(v[i].x, sws[(i * 4 + 0) * 8 + e], acc);
            acc = fmaf(v[i].y, sws[(i * 4 + 1) * 8 + e], acc);
            acc = fmaf(v[i].z, sws[(i * 4 + 2) * 8 + e], acc);
            acc = fmaf(v[i].w, sws[(i * 4 + 3) * 8 + e], acc);
        }
        g_wc[((h & 3) * 192 + (h >> 2)) * 8 + e] = acc;

        if (bid == 0 && tid < E) {
            float s = sw_b[tid];
#pragma unroll
            for (int r = 0; r < R; r++) s = fmaf(enc_b[r], sws[r * E + tid], s);
            g_bc[tid] = s;
            g_counts[tid] = 0;
        }
    } else if (bid < 120) {
        const float4* src = (const float4*)w1;
        float4* dst = (float4*)g_w1r;
#pragma unroll
        for (int i = 0; i < 4; i++) {
            int idx = (bid - 24) * 1024 + i * 256 + tid;
            float4 v = src[idx];
            v.x = tf32f(v.x); v.y = tf32f(v.y); v.z = tf32f(v.z); v.w = tf32f(v.w);
            dst[idx] = v;
        }
    } else {
        const float4* src = (const float4*)w2;
        float4* dst = (float4*)g_w2r;
#pragma unroll
        for (int i = 0; i < 4; i++) {
            int idx = (bid - 120) * 1024 + i * 256 + tid;
            float4 v = src[idx];
            v.x = tf32f(v.x); v.y = tf32f(v.y); v.z = tf32f(v.z); v.w = tf32f(v.w);
            dst[idx] = v;
        }
    }
}

// ---------------- router: logits = x @ W_comb + b_comb ----------------------
// Block-aggregated bucketing: smem slots + 8 global atomics per block.
__global__ __launch_bounds__(256) void router_lite_kernel(const float* __restrict__ x)
{
    __shared__ int s_cnt[8], s_base[8], s_am[32], s_slot[32];

    const int tid  = threadIdx.x;
    const int wid  = tid >> 5;
    const int lane = tid & 31;
    const int tb   = (blockIdx.x * 8 + wid) * 4;

    if (tid < 8) s_cnt[tid] = 0;

    float acc[4][8];
#pragma unroll
    for (int t = 0; t < 4; t++)
#pragma unroll
        for (int e = 0; e < 8; e++) acc[t][e] = 0.f;

    const float* xp0 = x + (size_t)tb * H + lane * 4;

#pragma unroll
    for (int j = 0; j < 6; j++) {
        float4 xv[4];
#pragma unroll
        for (int t = 0; t < 4; t++)
            xv[t] = *(const float4*)(xp0 + (size_t)t * H + j * 128);
#pragma unroll
        for (int c = 0; c < 4; c++) {
            const float* wrow = g_wc + ((size_t)(c * 192 + j * 32 + lane) * 8);
            float4 w0 = *(const float4*)wrow;
            float4 w1 = *(const float4*)(wrow + 4);
#pragma unroll
            for (int t = 0; t < 4; t++) {
                float xs = (c == 0) ? xv[t].x : (c == 1) ? xv[t].y
                          : (c == 2) ? xv[t].z : xv[t].w;
                acc[t][0] += xs * w0.x; acc[t][1] += xs * w0.y;
                acc[t][2] += xs * w0.z; acc[t][3] += xs * w0.w;
                acc[t][4] += xs * w1.x; acc[t][5] += xs * w1.y;
                acc[t][6] += xs * w1.z; acc[t][7] += xs * w1.w;
            }
        }
    }

    float a[32];
#pragma unroll
    for (int t = 0; t < 4; t++)
#pragma unroll
        for (int e = 0; e < 8; e++) a[t * 8 + e] = acc[t][e];

#pragma unroll
    for (int r = 0; r < 5; r++) {
        const int hn = 16 >> r;
        const bool up = (lane >> r) & 1;
#pragma unroll
        for (int j2 = 0; j2 < hn; j2++) {
            float pay  = up ? a[2 * j2] : a[2 * j2 + 1];
            float rec  = __shfl_xor_sync(0xffffffffu, pay, 1 << r);
            float keep = up ? a[2 * j2 + 1] : a[2 * j2];
            a[j2] = keep + rec;
        }
    }

    const int e    = lane & 7;
    const int tloc = lane >> 3;
    float l = a[0] + g_bc[e];

    float m = l; int am = e;
#pragma unroll
    for (int off = 4; off >= 1; off >>= 1) {
        float om = __shfl_xor_sync(0xffffffffu, m, off);
        int   oa = __shfl_xor_sync(0xffffffffu, am, off);
        if (om > m || (om == m && oa < am)) { m = om; am = oa; }
    }
    float s = expf(l - m);
#pragma unroll
    for (int off = 4; off >= 1; off >>= 1) s += __shfl_xor_sync(0xffffffffu, s, off);

    if (e == 0) {
        int tl = wid * 4 + tloc;
        s_am[tl] = am;
        g_pmax[tb + tloc] = 1.0f / s;
    }
    __syncthreads();

    if (tid < 32) {
        s_slot[tid] = atomicAdd(&s_cnt[s_am[tid]], 1);
    }
    __syncthreads();

    if (tid < 8 && s_cnt[tid] > 0)
        s_base[tid] = atomicAdd(&g_counts[tid], s_cnt[tid]);
    __syncthreads();

    if (tid < 32) {
        int am2 = s_am[tid];
        g_toks[am2 * T_TOT + s_base[am2] + s_slot[tid]] = blockIdx.x * 32 + tid;
    }
}

// ---------------- expert kernel: T_TILE=64, 2+ blocks/SM, cp.async ----------
// Warp grid 4(M)x2(N): warp (wm, wn) does rows wm*16..+16, cols wn*32..+32.
// smem (bytes), total 55552 -> 2+ blocks/SM:
//   pool @0 (36864): phase1 XS[2][64][36] (18432) + WS[2][32][72] @18432 (18432)
//                    phase2 W2S[2][64][72] (36864) overlays
//   HS @36864 (17408); TOK @54272; PM @54528; B1S @54784; B2S @55040
#define WS_OFF    18432
#define OFF_HS    36864
#define OFF_TOK   54272
#define OFF_PM    54528
#define OFF_B1S   54784
#define OFF_B2S   55040
#define SMEM_TOTAL 55552

#define XS_STR  36
#define WS_STR  72
#define HS_STR  68

#define EXPERT_BLOCKS 263   // sum ceil(cnt/64) <= 16384/64 + 7 = 263

__global__ void __launch_bounds__(256, 2)
expert_mma_kernel(const float* __restrict__ x,
                  const float* __restrict__ b1,
                  const float* __restrict__ b2, float* __restrict__ outp)
{
    extern __shared__ char smem[];

    // flat tile lookup: blockIdx.x -> (expert, token-chunk)
    int e = -1, t0 = 0, cnt = 0, accb = 0;
#pragma unroll
    for (int i = 0; i < 8; i++) {
        int c  = g_counts[i];
        int tl = (c + 63) >> 6;
        if (e < 0 && (int)blockIdx.x < accb + tl) {
            e = i; t0 = ((int)blockIdx.x - accb) << 6; cnt = c;
        }
        accb += tl;
    }
    if (e < 0) return;
    const int nt_lim = min(T_TILE, cnt - t0);

    const int tid  = threadIdx.x;
    const int wid  = tid >> 5;
    const int lane = tid & 31;
    const int lr   = lane >> 2;
    const int lc   = lane & 3;
    const int wm   = wid & 3;
    const int wn   = wid >> 2;
    const int m0   = wm * 16;
    const int nb   = wn * 32;

    const uint32_t sb = smem_u32(smem);
    float* SM   = (float*)smem;
    float* HSf  = (float*)(smem + OFF_HS);
    int*   toks = (int*)(smem + OFF_TOK);
    float* pm_s = (float*)(smem + OFF_PM);
    float* b1s  = (float*)(smem + OFF_B1S);
    float* b2s  = (float*)(smem + OFF_B2S);

    if (tid < 64) {
        int idx = t0 + ((tid < nt_lim) ? tid : 0);
        int tok = g_toks[e * T_TOT + idx];
        toks[tid] = tok;
        pm_s[tid] = g_pmax[tok];
        b1s[tid]  = b1[e * R + tid];
    }
    __syncthreads();

    // ======== Phase 1: C1[64,64] = X[64,768] @ W1[768,64] (2-stage) ========
    const float* w1e = g_w1r + (size_t)e * H * R;
    const float* xgp[2]; uint32_t xdst[2];
#pragma unroll
    for (int j = 0; j < 2; j++) {
        int i = tid + j * 256;
        int row = i >> 3, k4 = (i & 7) << 2;
        xgp[j]  = x + (size_t)toks[row] * H + k4;
        xdst[j] = sb + (uint32_t)(row * XS_STR + k4) * 4;
    }
    const float* wgp[2]; uint32_t wdst[2];
#pragma unroll
    for (int j = 0; j < 2; j++) {
        int i = tid + j * 256;
        int kr = i >> 4, n4 = (i & 15) << 2;
        wgp[j]  = w1e + (size_t)kr * R + n4;
        wdst[j] = sb + WS_OFF + (uint32_t)(kr * WS_STR + n4) * 4;
    }

#define P1_ISSUE(s, k0) { \
    _Pragma("unroll") for (int j = 0; j < 2; j++) \
        CP16(xdst[j] + (s) * 9216, xgp[j] + (k0)); \
    _Pragma("unroll") for (int j = 0; j < 2; j++) \
        CP16(wdst[j] + (s) * 9216, wgp[j] + (size_t)(k0) * R); \
    CP_COMMIT(); }

    float acc[4][4];
#pragma unroll
    for (int i = 0; i < 4; i++)
#pragma unroll
        for (int j = 0; j < 4; j++) acc[i][j] = 0.f;

    P1_ISSUE(0, 0);
    P1_ISSUE(1, 32);

    for (int it = 0; it < 24; it++) {
        const int p = it & 1;
        if (it < 23) { CP_WAIT1(); } else { CP_WAIT0(); }
        __syncthreads();
        const float* XA = SM + (size_t)p * 2304 + m0 * XS_STR;
        const float* WB = SM + ((WS_OFF >> 2) + p * 2304) + nb;
#pragma unroll
        for (int ks = 0; ks < 4; ks++) {
            const int kk = ks * 8;
            const float* xb = XA + kk;
            uint32_t a0 = FB(tf32f(xb[(size_t)lr * XS_STR + lc]));
            uint32_t a1 = FB(tf32f(xb[(size_t)(lr + 8) * XS_STR + lc]));
            uint32_t a2 = FB(tf32f(xb[(size_t)lr * XS_STR + lc + 4]));
            uint32_t a3 = FB(tf32f(xb[(size_t)(lr + 8) * XS_STR + lc + 4]));
            const float* wb0 = WB + (size_t)(kk + lc) * WS_STR + lr;
            const float* wb1 = WB + (size_t)(kk + lc + 4) * WS_STR + lr;
#pragma unroll
            for (int nt = 0; nt < 4; nt++) {
                uint32_t b0 = FB(wb0[nt * 8]);
                uint32_t b1v = FB(wb1[nt * 8]);
                mma_tf32(acc[nt], a0, a1, a2, a3, b0, b1v);
            }
        }
        if (it < 22) {
            __syncthreads();
            P1_ISSUE(p, (it + 2) * 32);
        }
    }
    __syncthreads();   // all phase-1 reads done before pool reuse

    // bias + gelu -> HS (tf32-rounded)
#pragma unroll
    for (int nt = 0; nt < 4; nt++) {
        const int cb = nb + nt * 8 + 2 * lc;
        const float bva = b1s[cb], bvb = b1s[cb + 1];
        float* h0 = HSf + (size_t)(m0 + lr) * HS_STR + cb;
        float* h1 = HSf + (size_t)(m0 + lr + 8) * HS_STR + cb;
        h0[0] = tf32f(gelu(acc[nt][0] + bva));
        h0[1] = tf32f(gelu(acc[nt][1] + bvb));
        h1[0] = tf32f(gelu(acc[nt][2] + bva));
        h1[1] = tf32f(gelu(acc[nt][3] + bvb));
    }
    __syncthreads();   // cross-warp: af needs full K columns

    // preload phase-2 A fragments (K=64)
    uint32_t af[8][4];
#pragma unroll
    for (int ks = 0; ks < 8; ks++) {
        const int kk = ks * 8;
        const float* hb = HSf + (size_t)m0 * HS_STR + kk;
        af[ks][0] = FB(hb[(size_t)lr * HS_STR + lc]);
        af[ks][1] = FB(hb[(size_t)(lr + 8) * HS_STR + lc]);
        af[ks][2] = FB(hb[(size_t)lr * HS_STR + lc + 4]);
        af[ks][3] = FB(hb[(size_t)(lr + 8) * HS_STR + lc + 4]);
    }

    // ======== Phase 2: out[64,768] = gelu_h[64,64] @ W2[64,768] ========
    const float* w2e = g_w2r + (size_t)e * R * H;
    const float* w2gp[4]; uint32_t w2dst[4];
#pragma unroll
    for (int j = 0; j < 4; j++) {
        int i = tid + j * 256;
        int kr = i >> 4, n4 = (i & 15) << 2;
        w2gp[j]  = w2e + (size_t)kr * H + n4;
        w2dst[j] = sb + (uint32_t)(kr * WS_STR + n4) * 4;
    }
#define P2_ISSUE(b, n0) { \
    _Pragma("unroll") for (int j = 0; j < 4; j++) \
        CP16(w2dst[j] + (b) * 18432, w2gp[j] + (n0)); \
    CP_COMMIT(); }

    const bool ok0 = (m0 + lr) < nt_lim;
    const bool ok1 = (m0 + lr + 8) < nt_lim;
    const float pm0 = pm_s[m0 + lr];
    const float pm1 = pm_s[m0 + lr + 8];
    float* orow0 = outp + (size_t)toks[m0 + lr] * H;
    float* orow1 = outp + (size_t)toks[m0 + lr + 8] * H;

    P2_ISSUE(0, 0);
    if (tid < 64) b2s[tid] = b2[(size_t)e * H + tid];

    for (int nc = 0; nc < 12; nc++) {
        const int bf = nc & 1;
        const int n0 = nc * 64;
        CP_WAIT0();
        __syncthreads();
        if (nc < 11) {
            P2_ISSUE(bf ^ 1, n0 + 64);
            if (tid < 64) b2s[(bf ^ 1) * 64 + tid] = b2[(size_t)e * H + n0 + 64 + tid];
        }

        float acc2[4][4];
#pragma unroll
        for (int i = 0; i < 4; i++)
#pragma unroll
            for (int j = 0; j < 4; j++) acc2[i][j] = 0.f;

        const float* W2B = SM + (size_t)bf * 4608 + nb;
#pragma unroll
        for (int ks = 0; ks < 8; ks++) {
            const int kk = ks * 8;
            const float* wb0 = W2B + (size_t)(kk + lc) * WS_STR + lr;
            const float* wb1 = W2B + (size_t)(kk + lc + 4) * WS_STR + lr;
#pragma unroll
            for (int nt = 0; nt < 4; nt++) {
                uint32_t b0 = FB(wb0[nt * 8]);
                uint32_t b1v = FB(wb1[nt * 8]);
                mma_tf32(acc2[nt], af[ks][0], af[ks][1], af[ks][2], af[ks][3], b0, b1v);
            }
        }

#pragma unroll
        for (int nt = 0; nt < 4; nt++) {
            const int cb = nb + nt * 8 + 2 * lc;
            const float bva = b2s[bf * 64 + cb], bvb = b2s[bf * 64 + cb + 1];
            if (ok0) {
                float2 o = { (acc2[nt][0] + bva) * pm0, (acc2[nt][1] + bvb) * pm0 };
                *(float2*)(orow0 + n0 + cb) = o;
            }
            if (ok1) {
                float2 o = { (acc2[nt][2] + bva) * pm1, (acc2[nt][3] + bvb) * pm1 };
                *(float2*)(orow1 + n0 + cb) = o;
            }
        }
    }
}

// ---------------- launch ----------------------------------------------------
extern "C" void kernel_launch(void* const* d_in, const int* in_sizes, int n_in,
                              void* d_out, int out_size) {
    const float* x     = (const float*)d_in[0];
    const float* enc_w = (const float*)d_in[1];
    const float* enc_b = (const float*)d_in[2];
    const float* sw_w  = (const float*)d_in[3];
    const float* sw_b  = (const float*)d_in[4];
    const float* w1    = (const float*)d_in[5];
    const float* b1    = (const float*)d_in[6];
    const float* w2    = (const float*)d_in[7];
    const float* b2    = (const float*)d_in[8];
    float* out = (float*)d_out;

    cudaFuncSetAttribute(expert_mma_kernel,
                         cudaFuncAttributeMaxDynamicSharedMemorySize, SMEM_TOTAL);

    router_prep_kernel<<<216, 256>>>(enc_w, enc_b, sw_w, sw_b, w1, w2);
    router_lite_kernel<<<T_TOT / 32, 256>>>(x);
    expert_mma_kernel<<<EXPERT_BLOCKS, 256, SMEM_TOTAL>>>(x, b1, b2, out);
}